// round 3
// baseline (speedup 1.0000x reference)
#include <cuda_runtime.h>
#include <cuda_bf16.h>
#include <cooperative_groups.h>
#include <cstdint>

namespace cg = cooperative_groups;

// Problem dims
#define NUM_C 1024
#define EMB   512
#define HID   512
#define BATCH 64
#define SEQ   512
#define M_ROWS (BATCH * SEQ)   // 32768

// ---------------------------------------------------------------------------
// Device scratch (allocation-free contract: __device__ globals)
// ---------------------------------------------------------------------------
__device__ float g_xproj[(size_t)M_ROWS * HID];   // 64 MB: Wx x + bx + bh
__device__ float g_hs   [(size_t)M_ROWS * HID];   // 64 MB: scan outputs

// ---------------------------------------------------------------------------
// xproj GEMM: out[m][n] = sum_e emb[idx[m]][e] * Wx_w[n][e] + Wx_b[n] + Wh_b[n]
// ---------------------------------------------------------------------------
__global__ __launch_bounds__(256, 2)
void xproj_kernel(const int* __restrict__ q, const int* __restrict__ r,
                  const float* __restrict__ emb,
                  const float* __restrict__ Wx_w,
                  const float* __restrict__ Wx_b,
                  const float* __restrict__ Wh_b) {
    __shared__ float As[8][128];
    __shared__ float Bs[8][128];
    __shared__ int   sidx[128];

    const int tid  = threadIdx.x;
    const int row0 = blockIdx.y * 128;
    const int col0 = blockIdx.x * 128;

    if (tid < 128) {
        int m = row0 + tid;
        sidx[tid] = q[m] + NUM_C * r[m];
    }
    __syncthreads();

    const int lr = tid >> 1;
    const int lc = (tid & 1) * 4;
    const int tx = tid & 15;
    const int ty = tid >> 4;

    const int arow = sidx[lr];

    const float* aptr = emb  + (size_t)arow        * EMB;
    const float* bptr = Wx_w + (size_t)(col0 + lr) * EMB;

    float acc[8][8];
#pragma unroll
    for (int i = 0; i < 8; i++)
#pragma unroll
        for (int j = 0; j < 8; j++) acc[i][j] = 0.0f;

    float4 pa = *(const float4*)(aptr + lc);
    float4 pb = *(const float4*)(bptr + lc);

    for (int k0 = 0; k0 < EMB; k0 += 8) {
        __syncthreads();
        As[lc + 0][lr] = pa.x; As[lc + 1][lr] = pa.y;
        As[lc + 2][lr] = pa.z; As[lc + 3][lr] = pa.w;
        Bs[lc + 0][lr] = pb.x; Bs[lc + 1][lr] = pb.y;
        Bs[lc + 2][lr] = pb.z; Bs[lc + 3][lr] = pb.w;
        __syncthreads();

        if (k0 + 8 < EMB) {
            pa = *(const float4*)(aptr + k0 + 8 + lc);
            pb = *(const float4*)(bptr + k0 + 8 + lc);
        }

#pragma unroll
        for (int k = 0; k < 8; k++) {
            float ra[8], rb[8];
#pragma unroll
            for (int i = 0; i < 8; i++) ra[i] = As[k][ty * 8 + i];
#pragma unroll
            for (int j = 0; j < 8; j++) rb[j] = Bs[k][tx * 8 + j];
#pragma unroll
            for (int i = 0; i < 8; i++)
#pragma unroll
                for (int j = 0; j < 8; j++) acc[i][j] += ra[i] * rb[j];
        }
    }

#pragma unroll
    for (int i = 0; i < 8; i++) {
        int m = row0 + ty * 8 + i;
        float* op = g_xproj + (size_t)m * HID + col0 + tx * 8;
#pragma unroll
        for (int j = 0; j < 8; j++) {
            int n = col0 + tx * 8 + j;
            op[j] = acc[i][j] + Wx_b[n] + Wh_b[n];
        }
    }
}

// ---------------------------------------------------------------------------
// Cluster-based persistent scan.
// 16 clusters x 8 CTAs. Cluster = 4 batch rows (independent -> no global sync).
// Rank = 64-column j-slice; Wh slice resident in smem (130 KB).
// Full h[512][4] double-buffered in EVERY rank's smem; after each step each
// rank broadcasts its 64-row h slice into peers' smem via DSMEM, then
// cluster.sync(). Packed fma.rn.f32x2 halves FMA issue.
// ---------------------------------------------------------------------------
#define SW_PAD 65
#define SCAN_SMEM_FLOATS (512 * SW_PAD + 2 * 512 * 4 + 4 * 4 * 64)
#define SCAN_SMEM_BYTES  (SCAN_SMEM_FLOATS * 4)   // 153,600 B

__global__ __launch_bounds__(256, 1) __cluster_dims__(8, 1, 1)
void scan_kernel(const float* __restrict__ Wh_w,
                 const float* __restrict__ tau) {
    extern __shared__ float smem[];
    float* sw   = smem;                      // [512 k][65]   Wh slice (transposed)
    float* sh   = smem + 512 * SW_PAD;       // [2][512 k][4 b] h double buffer
    float* sred = sh + 2 * 512 * 4;          // [4 ks][4 b][64 jl]

    cg::cluster_group cluster = cg::this_cluster();
    const int rank = (int)cluster.block_rank();   // 0..7 -> j slice
    const int cid  = blockIdx.x >> 3;             // 0..15 -> batch slice
    const int tid  = threadIdx.x;
    const int j0   = rank * 64;
    const int b0   = cid * 4;

    // ---- load Wh slice transposed into smem: sw[k][jl] = Wh[j0+jl][k] ----
    {
        const int jl = tid & 63;
        const int kq = tid >> 6;                  // 0..3
        const float* wrow = Wh_w + (size_t)(j0 + jl) * HID + kq * 128;
#pragma unroll
        for (int p = 0; p < 32; p++) {
            float4 wv = *(const float4*)(wrow + p * 4);
            int k4 = kq * 128 + p * 4;
            sw[(k4 + 0) * SW_PAD + jl] = wv.x;
            sw[(k4 + 1) * SW_PAD + jl] = wv.y;
            sw[(k4 + 2) * SW_PAD + jl] = wv.z;
            sw[(k4 + 3) * SW_PAD + jl] = wv.w;
        }
    }
    // ---- zero h buffer 0 ----
    for (int i = tid; i < 512 * 4; i += 256) sh[i] = 0.0f;

    const int jl  = tid & 63;                // column lane (phase A and B)
    const int ks  = tid >> 6;                // k-slice (phase A)
    const int b_o = tid >> 6;                // batch row (phase B)
    const float itau = 1.0f / tau[j0 + jl];

    __syncthreads();
    cluster.sync();

    for (int s = 0; s < SEQ; s++) {
        const float* shc = sh + (s & 1) * 2048;
        float*       shn = sh + ((s + 1) & 1) * 2048;

        // prefetch xp for this step (independent of h; hidden by FMA loop)
        float xp = __ldcg(&g_xproj[((size_t)(b0 + b_o) * SEQ + s) * HID + j0 + jl]);

        // ---- phase A: partial GEMM over this thread's 128-k slice ----
        // acc pairs: (b0,b1) and (b2,b3) as packed f32x2
        unsigned long long acc01 = 0ull, acc23 = 0ull;
        const float* wp = sw + (ks * 128) * SW_PAD + jl;
        const float* hp = shc + ks * 128 * 4;
#pragma unroll 8
        for (int kk = 0; kk < 128; kk++) {
            float w = wp[kk * SW_PAD];
            unsigned wu = __float_as_uint(w);
            unsigned long long ww;
            asm("mov.b64 %0, {%1, %1};" : "=l"(ww) : "r"(wu));
            ulonglong2 h2 = *(const ulonglong2*)(hp + kk * 4);  // broadcast
            asm("fma.rn.f32x2 %0, %1, %2, %0;" : "+l"(acc01) : "l"(h2.x), "l"(ww));
            asm("fma.rn.f32x2 %0, %1, %2, %0;" : "+l"(acc23) : "l"(h2.y), "l"(ww));
        }
        {
            unsigned a0, a1, a2, a3;
            asm("mov.b64 {%0, %1}, %2;" : "=r"(a0), "=r"(a1) : "l"(acc01));
            asm("mov.b64 {%0, %1}, %2;" : "=r"(a2), "=r"(a3) : "l"(acc23));
            float* rp = sred + ks * 256 + jl;
            rp[0]   = __uint_as_float(a0);
            rp[64]  = __uint_as_float(a1);
            rp[128] = __uint_as_float(a2);
            rp[192] = __uint_as_float(a3);
        }
        __syncthreads();

        // ---- phase B: reduce 4 k-slices, LTC cell update ----
        float sum = sred[0 * 256 + b_o * 64 + jl] + sred[1 * 256 + b_o * 64 + jl]
                  + sred[2 * 256 + b_o * 64 + jl] + sred[3 * 256 + b_o * 64 + jl];
        float z    = sum + xp;
        float th   = tanhf(z);
        float hold = shc[(j0 + jl) * 4 + b_o];
        float hn   = hold + (th - hold) * itau;

        g_hs[((size_t)(b0 + b_o) * SEQ + s) * HID + j0 + jl] = hn;
        shn[(j0 + jl) * 4 + b_o] = hn;     // own slice of next-h, local
        __syncthreads();

        // ---- phase C: broadcast own 64-row h slice to the 7 peers ----
        if (s < SEQ - 1) {
            if (tid < 64) {
                float4* src = (float4*)&shn[(j0 + tid) * 4];
                float4  v   = *src;
#pragma unroll
                for (int rk = 0; rk < 8; rk++) {
                    if (rk == rank) continue;
                    float4* dst = cluster.map_shared_rank(src, rk);
                    *dst = v;
                }
            }
            cluster.sync();
        }
    }
}

// ---------------------------------------------------------------------------
// Output GEMM + sigmoid: y[m][c] = sigmoid(sum_h hs[m][h]*Wo_w[c][h] + Wo_b[c])
// ---------------------------------------------------------------------------
__global__ __launch_bounds__(256, 2)
void out_kernel(const float* __restrict__ Wo_w,
                const float* __restrict__ Wo_b,
                float* __restrict__ out) {
    __shared__ float As[8][128];
    __shared__ float Bs[8][128];

    const int tid  = threadIdx.x;
    const int row0 = blockIdx.y * 128;
    const int col0 = blockIdx.x * 128;

    const int lr = tid >> 1;
    const int lc = (tid & 1) * 4;
    const int tx = tid & 15;
    const int ty = tid >> 4;

    const float* aptr = g_hs + (size_t)(row0 + lr) * HID;
    const float* bptr = Wo_w + (size_t)(col0 + lr) * HID;

    float acc[8][8];
#pragma unroll
    for (int i = 0; i < 8; i++)
#pragma unroll
        for (int j = 0; j < 8; j++) acc[i][j] = 0.0f;

    float4 pa = *(const float4*)(aptr + lc);
    float4 pb = *(const float4*)(bptr + lc);

    for (int k0 = 0; k0 < HID; k0 += 8) {
        __syncthreads();
        As[lc + 0][lr] = pa.x; As[lc + 1][lr] = pa.y;
        As[lc + 2][lr] = pa.z; As[lc + 3][lr] = pa.w;
        Bs[lc + 0][lr] = pb.x; Bs[lc + 1][lr] = pb.y;
        Bs[lc + 2][lr] = pb.z; Bs[lc + 3][lr] = pb.w;
        __syncthreads();

        if (k0 + 8 < HID) {
            pa = *(const float4*)(aptr + k0 + 8 + lc);
            pb = *(const float4*)(bptr + k0 + 8 + lc);
        }

#pragma unroll
        for (int k = 0; k < 8; k++) {
            float ra[8], rb[8];
#pragma unroll
            for (int i = 0; i < 8; i++) ra[i] = As[k][ty * 8 + i];
#pragma unroll
            for (int j = 0; j < 8; j++) rb[j] = Bs[k][tx * 8 + j];
#pragma unroll
            for (int i = 0; i < 8; i++)
#pragma unroll
                for (int j = 0; j < 8; j++) acc[i][j] += ra[i] * rb[j];
        }
    }

#pragma unroll
    for (int i = 0; i < 8; i++) {
        int m = row0 + ty * 8 + i;
        float* op = out + (size_t)m * NUM_C + col0 + tx * 8;
#pragma unroll
        for (int j = 0; j < 8; j++) {
            int n = col0 + tx * 8 + j;
            float logit = acc[i][j] + Wo_b[n];
            op[j] = 1.0f / (1.0f + expf(-logit));
        }
    }
}

// ---------------------------------------------------------------------------
extern "C" void kernel_launch(void* const* d_in, const int* in_sizes, int n_in,
                              void* d_out, int out_size) {
    const int*   q    = (const int*)  d_in[0];
    const int*   r    = (const int*)  d_in[1];
    const float* emb  = (const float*)d_in[2];
    const float* Wh_w = (const float*)d_in[3];
    const float* Wh_b = (const float*)d_in[4];
    const float* Wx_w = (const float*)d_in[5];
    const float* Wx_b = (const float*)d_in[6];
    const float* tau  = (const float*)d_in[7];
    const float* Wo_w = (const float*)d_in[8];
    const float* Wo_b = (const float*)d_in[9];
    float*       out  = (float*)d_out;

    // idempotent, capture-legal
    cudaFuncSetAttribute(scan_kernel,
                         cudaFuncAttributeMaxDynamicSharedMemorySize,
                         SCAN_SMEM_BYTES);

    // 1) input projection GEMM (gather fused)
    {
        dim3 grid(HID / 128, M_ROWS / 128);
        xproj_kernel<<<grid, 256>>>(q, r, emb, Wx_w, Wx_b, Wh_b);
    }
    // 2) cluster scan: 128 CTAs = 16 clusters x 8 ranks
    scan_kernel<<<128, 256, SCAN_SMEM_BYTES>>>(Wh_w, tau);
    // 3) output GEMM + sigmoid
    {
        dim3 grid(NUM_C / 128, M_ROWS / 128);
        out_kernel<<<grid, 256>>>(Wo_w, Wo_b, out);
    }
}